// round 3
// baseline (speedup 1.0000x reference)
#include <cuda_runtime.h>

typedef unsigned long long ull;

// ---------------- problem constants ----------------
#define TT    1024
#define BB    64
#define WW    512
#define W3    1536
#define LL    2

// ---------------- kernel config --------------------
#define GRID    128     // 64 CTAs per GEMM-group; all co-resident (<=148 SMs, 1 CTA/SM)
#define NTH     256
#define NGC     8       // gate-columns per CTA (64*8 = 512)
#define NCOLS   (NGC*3) // 24 actual weight columns per CTA
#define CHUNK   64      // K-chunk staged in smem
#define NCHUNK  16      // K = 1024
#define AS      68      // A smem row stride (pad 4 floats -> conflict-free, 16B-aligned)
#define WS      1028    // W smem row stride (pad 4 floats -> conflict-free, 16B-aligned)

#define SMEM_FLOATS (NCOLS*WS + 2*BB*AS + BB)
#define SMEM_BYTES  (SMEM_FLOATS * 4)

// ---------------- persistent device state ----------
__device__ float g_h0[2][BB * WW];      // double-buffered layer-0 hidden
__device__ float g_h1[2][BB * WW];      // double-buffered layer-1 hidden
__device__ unsigned g_cnt = 0;          // barrier arrival counter (self-resetting)
__device__ volatile unsigned g_gen = 0; // barrier generation (monotonic across launches)
__device__ int g_reset_mode = 0;        // 0=uint8/bool, 1=int32, 2=float32

// ---------------- reset dtype sniffing --------------
// bool/uint8 bytes: uint32 view gives combos of 0x00/0x01 bytes (max in (1, 0x01010101]).
// int32 0/1: max <= 1.  float32 0/1.0f: max = 0x3F800000.
__global__ void sniff_resets_kernel(const unsigned* __restrict__ r)
{
    __shared__ unsigned red[256];
    unsigned m = 0;
    for (int i = threadIdx.x; i < (TT * BB) / 4; i += 256)
        m = max(m, r[i]);
    red[threadIdx.x] = m;
    __syncthreads();
    for (int s = 128; s > 0; s >>= 1) {
        if (threadIdx.x < s) red[threadIdx.x] = max(red[threadIdx.x], red[threadIdx.x + s]);
        __syncthreads();
    }
    if (threadIdx.x == 0) {
        unsigned mx = red[0];
        g_reset_mode = (mx <= 1u) ? 1 : (mx >= 0x10000000u ? 2 : 0);
    }
}

__device__ __forceinline__ float reset_mask(const void* r, int mode, int idx)
{
    if (mode == 1) return ((const int*)r)[idx] != 0 ? 0.0f : 1.0f;
    if (mode == 2) return ((const float*)r)[idx] != 0.0f ? 0.0f : 1.0f;
    return ((const unsigned char*)r)[idx] != 0 ? 0.0f : 1.0f;
}

// ---------------- packed f32x2 FMA ------------------
__device__ __forceinline__ void ffma2(ull& acc, ull a, ull b)
{
    asm("fma.rn.f32x2 %0, %1, %2, %0;" : "+l"(acc) : "l"(a), "l"(b));
}
__device__ __forceinline__ float hadd2(ull v)
{
    return __uint_as_float((unsigned)v) + __uint_as_float((unsigned)(v >> 32));
}

// --------------- inner product over one K-chunk -----
// per thread: 2 batch rows x 3 gate columns, K-packed by 2 via f32x2
__device__ __forceinline__ void mma_chunk(
    const float* __restrict__ As,
    const float* __restrict__ wr, const float* __restrict__ wz, const float* __restrict__ wn,
    int kbase, int b0o, int b1o,
    ull& r0, ull& r1, ull& z0, ull& z1, ull& n0, ull& n1)
{
#pragma unroll
    for (int kk = 0; kk < CHUNK; kk += 4) {
        float4 a0 = *(const float4*)(As + b0o + kk);
        float4 a1 = *(const float4*)(As + b1o + kk);
        float4 fr = *(const float4*)(wr + kbase + kk);
        float4 fz = *(const float4*)(wz + kbase + kk);
        float4 fn = *(const float4*)(wn + kbase + kk);
        const ull* a0p = (const ull*)&a0;
        const ull* a1p = (const ull*)&a1;
        const ull* frp = (const ull*)&fr;
        const ull* fzp = (const ull*)&fz;
        const ull* fnp = (const ull*)&fn;
        ffma2(r0, a0p[0], frp[0]); ffma2(r0, a0p[1], frp[1]);
        ffma2(r1, a1p[0], frp[0]); ffma2(r1, a1p[1], frp[1]);
        ffma2(z0, a0p[0], fzp[0]); ffma2(z0, a0p[1], fzp[1]);
        ffma2(z1, a1p[0], fzp[0]); ffma2(z1, a1p[1], fzp[1]);
        ffma2(n0, a0p[0], fnp[0]); ffma2(n0, a0p[1], fnp[1]);
        ffma2(n1, a1p[0], fnp[0]); ffma2(n1, a1p[1], fnp[1]);
    }
}

__global__ void __launch_bounds__(NTH, 1)
gru_scan_kernel(const float* __restrict__ ins,
                const void* __restrict__ resets,
                const float* __restrict__ Wi, const float* __restrict__ bi,
                const float* __restrict__ Wh, const float* __restrict__ bhn,
                float* __restrict__ out)
{
    extern __shared__ float smem[];
    float* Wsm = smem;                       // [NCOLS][WS]   transposed weights
    float* Asm = smem + NCOLS * WS;          // [2][BB][AS]   double-buffered A chunk
    float* rm  = Asm  + 2 * BB * AS;         // [BB]          per-batch reset mask

    const int tid   = threadIdx.x;
    const int cta   = blockIdx.x;
    const int group = cta >> 6;              // 0: layer-1 task, 1: layer-0 task
    const int lyr   = (group == 0) ? 1 : 0;
    const int gwBase = (cta & 63) * NGC;
    const int tn = tid & 7;                  // gate-column within CTA
    const int tm = tid >> 3;                 // batch pair
    const int b0 = tm * 2, b1 = tm * 2 + 1;
    const int w  = gwBase + tn;              // global gate column [0,512)
    const int rmode = g_reset_mode;

    // ---- one-time: load this CTA's weight slice into smem, transposed [n][k] ----
    // Wcat[k][c]: k<512 -> Wi[lyr][k][c], else Wh[lyr][k-512][c]
    const float* WiL = Wi + (size_t)lyr * WW * W3;
    const float* WhL = Wh + (size_t)lyr * WW * W3;
    for (int idx = tid; idx < NCOLS * WW * 2; idx += NTH) {
        int n = idx % NCOLS;
        int k = idx / NCOLS;
        int gl = n / 3, gate = n - gl * 3;
        int c = gwBase + gl + gate * WW;
        float v = (k < WW) ? WiL[(size_t)k * W3 + c] : WhL[(size_t)(k - WW) * W3 + c];
        Wsm[n * WS + k] = v;
    }
    const float bir  = bi[lyr * W3 + w];
    const float biz  = bi[lyr * W3 + WW + w];
    const float bin  = bi[lyr * W3 + 2 * WW + w];
    const float bhnw = bhn[lyr * WW + w];

    unsigned gen = 0;
    if (tid == 0) gen = g_gen;               // per-launch barrier base (monotonic)
    __syncthreads();                         // weights + gen ready

    float* out_carry = out;                  // [L][B][W]
    float* out_ys    = out + LL * BB * WW;   // [T][B][W]

    const float* wr = &Wsm[(tn * 3 + 0) * WS];
    const float* wz = &Wsm[(tn * 3 + 1) * WS];
    const float* wn = &Wsm[(tn * 3 + 2) * WS];
    const int b0o = b0 * AS, b1o = b1 * AS;
    const int lb  = tid >> 2;                // loader: row
    const int lf0 = tid & 3;                 // loader: float4 phase

    // phase p: group1 computes layer0(t=p) for p<T; group0 computes layer1(t=p-1) for p>=1
    for (int p = 0; p <= TT; ++p) {
        const bool active = (group == 1) ? (p < TT) : (p >= 1);
        if (active) {
            const int t = (group == 1) ? p : (p - 1);
            const float* srcI = (group == 1) ? (ins + (size_t)t * BB * WW)
                                             : &g_h0[(p - 1) & 1][0];
            const float* srcH = (group == 1) ? &g_h0[(p == 0) ? 1 : ((p - 1) & 1)][0]
                                             : &g_h1[(p - 1) & 1][0];
            const bool zeroH = (group == 1) ? (p == 0) : (p == 1);

            if (tid < BB) {
                float m = 0.0f;
                if (!zeroH) m = reset_mask(resets, rmode, t * BB + tid);
                rm[tid] = m;
            }
            __syncthreads();

            ull r0 = 0, r1 = 0, z0 = 0, z1 = 0;
            ull ni0 = 0, ni1 = 0, nh0 = 0, nh1 = 0;

            // ---- stage chunk 0 (I-half, never masked) ----
            {
#pragma unroll
                for (int it = 0; it < 4; ++it) {
                    int f4 = lf0 + it * 4;
                    float4 v = __ldcg((const float4*)(srcI + (size_t)lb * WW + f4 * 4));
                    *(float4*)(Asm + lb * AS + f4 * 4) = v;
                }
            }
            __syncthreads();

            float4 pf[4]; float pm = 1.0f;
            for (int c = 0; c < NCHUNK; ++c) {
                if (c + 1 < NCHUNK) {        // prefetch next chunk into registers
                    int cn = c + 1;
                    const float* src = (cn < 8) ? srcI : srcH;
                    int kOff = (cn < 8) ? cn * CHUNK : (cn - 8) * CHUNK;
                    pm = (cn < 8) ? 1.0f : rm[lb];
#pragma unroll
                    for (int it = 0; it < 4; ++it) {
                        int f4 = lf0 + it * 4;
                        pf[it] = __ldcg((const float4*)(src + (size_t)lb * WW + kOff + f4 * 4));
                    }
                }
                const float* As = Asm + (c & 1) * BB * AS;
                if (c < 8) mma_chunk(As, wr, wz, wn, c * CHUNK, b0o, b1o, r0, r1, z0, z1, ni0, ni1);
                else       mma_chunk(As, wr, wz, wn, c * CHUNK, b0o, b1o, r0, r1, z0, z1, nh0, nh1);
                if (c + 1 < NCHUNK) {        // commit prefetch to the other buffer
                    float* dst = Asm + ((c + 1) & 1) * BB * AS;
#pragma unroll
                    for (int it = 0; it < 4; ++it) {
                        int f4 = lf0 + it * 4;
                        float4 v = pf[it];
                        *(float4*)(dst + lb * AS + f4 * 4) =
                            make_float4(v.x * pm, v.y * pm, v.z * pm, v.w * pm);
                    }
                }
                __syncthreads();
            }

            // ---- gates + state update (local: this thread owns {w, w+512, w+1024}) ----
            const float m0 = rm[b0], m1 = rm[b1];
            const float hp0 = __ldcg(srcH + b0 * WW + w) * m0;
            const float hp1 = __ldcg(srcH + b1 * WW + w) * m1;
            const float gr0 = bir + hadd2(r0), gr1 = bir + hadd2(r1);
            const float gz0 = biz + hadd2(z0), gz1 = biz + hadd2(z1);
            const float gi0 = bin + hadd2(ni0), gi1 = bin + hadd2(ni1);
            const float gh0 = hadd2(nh0), gh1 = hadd2(nh1);
            const float rr0 = 1.0f / (1.0f + expf(-gr0));
            const float rr1 = 1.0f / (1.0f + expf(-gr1));
            const float zz0 = 1.0f / (1.0f + expf(-gz0));
            const float zz1 = 1.0f / (1.0f + expf(-gz1));
            const float nn0 = tanhf(gi0 + rr0 * (gh0 + bhnw));
            const float nn1 = tanhf(gi1 + rr1 * (gh1 + bhnw));
            const float hnew0 = (1.0f - zz0) * nn0 + zz0 * hp0;
            const float hnew1 = (1.0f - zz1) * nn1 + zz1 * hp1;

            float* dst = (group == 1) ? &g_h0[p & 1][0] : &g_h1[p & 1][0];
            dst[b0 * WW + w] = hnew0;
            dst[b1 * WW + w] = hnew1;
            if (group == 0) {
                out_ys[(size_t)t * BB * WW + b0 * WW + w] = hnew0;
                out_ys[(size_t)t * BB * WW + b1 * WW + w] = hnew1;
                if (p == TT) {               // final h1 carry
                    out_carry[1 * BB * WW + b0 * WW + w] = hnew0;
                    out_carry[1 * BB * WW + b1 * WW + w] = hnew1;
                }
            } else if (p == TT - 1) {        // final h0 carry
                out_carry[b0 * WW + w] = hnew0;
                out_carry[b1 * WW + w] = hnew1;
            }
        }

        // ---- grid barrier (self-resetting counter + monotonic generation) ----
        __syncthreads();
        if (tid == 0) {
            __threadfence();
            unsigned a = atomicAdd(&g_cnt, 1);
            gen += 1;
            if (a == GRID - 1) {
                g_cnt = 0;
                __threadfence();
                g_gen = gen;
            } else {
                while (g_gen < gen) { __nanosleep(20); }
                __threadfence();
            }
        }
        __syncthreads();
    }
}

extern "C" void kernel_launch(void* const* d_in, const int* in_sizes, int n_in,
                              void* d_out, int out_size)
{
    const float* ins    = (const float*)d_in[0];
    const void*  resets = (const void*)d_in[1];
    const float* Wi     = (const float*)d_in[2];
    const float* bi     = (const float*)d_in[3];
    const float* Wh     = (const float*)d_in[4];
    const float* bhn    = (const float*)d_in[5];
    float*       out    = (float*)d_out;

    sniff_resets_kernel<<<1, 256>>>((const unsigned*)resets);

    cudaFuncSetAttribute(gru_scan_kernel,
                         cudaFuncAttributeMaxDynamicSharedMemorySize, SMEM_BYTES);
    gru_scan_kernel<<<GRID, NTH, SMEM_BYTES>>>(ins, resets, Wi, bi, Wh, bhn, out);
}

// round 4
// speedup vs baseline: 1.0574x; 1.0574x over previous
#include <cuda_runtime.h>

typedef unsigned long long ull;

// ---------------- problem constants ----------------
#define TT    1024
#define BB    64
#define WW    512
#define W3    1536
#define LL    2

// ---------------- kernel config --------------------
#define GRID    128     // 64 CTAs per GEMM-group; all co-resident, 1 CTA/SM
#define NTH     512     // 2 K-slices x 256
#define NGC     8       // gate-triples per CTA (64*8 = 512 columns)
#define NCOLS   (NGC*3) // 24 weight columns per CTA
#define CHUNK   64      // K-chunk staged in smem
#define NCH_S   8       // chunks per K-slice (16 total / 2 slices)
#define AS      68      // A smem row stride (pad -> conflict-free, 16B-aligned)
#define WS      1028    // W smem row stride (pad -> conflict-free, 16B-aligned)

// smem layout (floats): W | A[2 slices][2 bufs][BB*AS] | rm[BB] | red[256*8]
#define SMEM_W      (NCOLS*WS)
#define SMEM_A      (SMEM_W)
#define SMEM_RM     (SMEM_A + 4*BB*AS)
#define SMEM_RED    (SMEM_RM + BB)
#define SMEM_FLOATS (SMEM_RED + 256*8)
#define SMEM_BYTES  (SMEM_FLOATS * 4)

// ---------------- persistent device state ----------
__device__ float g_h0[2][BB * WW];      // double-buffered layer-0 hidden
__device__ float g_h1[2][BB * WW];      // double-buffered layer-1 hidden
__device__ unsigned g_cnt = 0;          // barrier arrival counter (self-resetting)
__device__ volatile unsigned g_gen = 0; // barrier generation (monotonic across launches)
__device__ int g_reset_mode = 0;        // 0=uint8/bool, 1=int32, 2=float32

// ---------------- reset dtype sniffing --------------
__global__ void sniff_resets_kernel(const unsigned* __restrict__ r)
{
    __shared__ unsigned red[256];
    unsigned m = 0;
    for (int i = threadIdx.x; i < (TT * BB) / 4; i += 256)
        m = max(m, r[i]);
    red[threadIdx.x] = m;
    __syncthreads();
    for (int s = 128; s > 0; s >>= 1) {
        if (threadIdx.x < s) red[threadIdx.x] = max(red[threadIdx.x], red[threadIdx.x + s]);
        __syncthreads();
    }
    if (threadIdx.x == 0) {
        unsigned mx = red[0];
        g_reset_mode = (mx <= 1u) ? 1 : (mx >= 0x10000000u ? 2 : 0);
    }
}

__device__ __forceinline__ float reset_mask(const void* r, int mode, int idx)
{
    if (mode == 1) return ((const int*)r)[idx] != 0 ? 0.0f : 1.0f;
    if (mode == 2) return ((const float*)r)[idx] != 0.0f ? 0.0f : 1.0f;
    return ((const unsigned char*)r)[idx] != 0 ? 0.0f : 1.0f;
}

// ---------------- packed f32x2 FMA ------------------
__device__ __forceinline__ void ffma2(ull& acc, ull a, ull b)
{
    asm("fma.rn.f32x2 %0, %1, %2, %0;" : "+l"(acc) : "l"(a), "l"(b));
}
__device__ __forceinline__ float hadd2(ull v)
{
    return __uint_as_float((unsigned)v) + __uint_as_float((unsigned)(v >> 32));
}

// slice-scoped named barrier (256 threads each)
__device__ __forceinline__ void slice_bar(int id)
{
    asm volatile("bar.sync %0, %1;" :: "r"(id), "r"(256) : "memory");
}

// --------------- inner product over one K-chunk -----
// per thread: 2 batch rows x 3 gate columns, K-packed by 2 via f32x2
__device__ __forceinline__ void mma_chunk(
    const float* __restrict__ As,
    const float* __restrict__ wr, const float* __restrict__ wz, const float* __restrict__ wn,
    int kbase, int b0o, int b1o,
    ull& r0, ull& r1, ull& z0, ull& z1, ull& n0, ull& n1)
{
#pragma unroll
    for (int kk = 0; kk < CHUNK; kk += 4) {
        float4 a0 = *(const float4*)(As + b0o + kk);
        float4 a1 = *(const float4*)(As + b1o + kk);
        float4 fr = *(const float4*)(wr + kbase + kk);
        float4 fz = *(const float4*)(wz + kbase + kk);
        float4 fn = *(const float4*)(wn + kbase + kk);
        const ull* a0p = (const ull*)&a0;
        const ull* a1p = (const ull*)&a1;
        const ull* frp = (const ull*)&fr;
        const ull* fzp = (const ull*)&fz;
        const ull* fnp = (const ull*)&fn;
        ffma2(r0, a0p[0], frp[0]); ffma2(r0, a0p[1], frp[1]);
        ffma2(r1, a1p[0], frp[0]); ffma2(r1, a1p[1], frp[1]);
        ffma2(z0, a0p[0], fzp[0]); ffma2(z0, a0p[1], fzp[1]);
        ffma2(z1, a1p[0], fzp[0]); ffma2(z1, a1p[1], fzp[1]);
        ffma2(n0, a0p[0], fnp[0]); ffma2(n0, a0p[1], fnp[1]);
        ffma2(n1, a1p[0], fnp[0]); ffma2(n1, a1p[1], fnp[1]);
    }
}

__global__ void __launch_bounds__(NTH, 1)
gru_scan_kernel(const float* __restrict__ ins,
                const void* __restrict__ resets,
                const float* __restrict__ Wi, const float* __restrict__ bi,
                const float* __restrict__ Wh, const float* __restrict__ bhn,
                float* __restrict__ out)
{
    extern __shared__ float smem[];
    float* Wsm = smem;                       // [NCOLS][WS]   transposed weights
    float* rm  = smem + SMEM_RM;             // [BB]          per-batch reset mask
    float* red = smem + SMEM_RED;            // [256][8]      slice-1 partial sums

    const int tid   = threadIdx.x;
    const int slice = tid >> 8;              // K-slice 0/1
    const int stid  = tid & 255;
    const int cta   = blockIdx.x;
    const int group = cta >> 6;              // 0: layer-1 task, 1: layer-0 task
    const int lyr   = (group == 0) ? 1 : 0;
    const int gwBase = (cta & 63) * NGC;
    const int tn = stid & 7;                 // gate-triple within CTA
    const int tm = stid >> 3;                // batch pair
    const int b0 = tm * 2, b1 = tm * 2 + 1;
    const int w  = gwBase + tn;              // global gate column [0,512)
    const int rmode = g_reset_mode;

    float* Asl = smem + SMEM_A + slice * (2 * BB * AS);  // this slice's A double buffer

    // ---- one-time: load this CTA's weight slice into smem, transposed [n][k] ----
    const float* WiL = Wi + (size_t)lyr * WW * W3;
    const float* WhL = Wh + (size_t)lyr * WW * W3;
    for (int idx = tid; idx < NCOLS * WW * 2; idx += NTH) {
        int n = idx % NCOLS;
        int k = idx / NCOLS;
        int gl = n / 3, gate = n - gl * 3;
        int c = gwBase + gl + gate * WW;
        float v = (k < WW) ? WiL[(size_t)k * W3 + c] : WhL[(size_t)(k - WW) * W3 + c];
        Wsm[n * WS + k] = v;
    }
    const float bir  = bi[lyr * W3 + w];
    const float biz  = bi[lyr * W3 + WW + w];
    const float bin  = bi[lyr * W3 + 2 * WW + w];
    const float bhnw = bhn[lyr * WW + w];

    unsigned gen = 0;
    if (tid == 0) gen = g_gen;               // per-launch barrier base (monotonic)
    __syncthreads();                         // weights + gen ready

    float* out_carry = out;                  // [L][B][W]
    float* out_ys    = out + LL * BB * WW;   // [T][B][W]

    const float* wr = &Wsm[(tn * 3 + 0) * WS];
    const float* wz = &Wsm[(tn * 3 + 1) * WS];
    const float* wn = &Wsm[(tn * 3 + 2) * WS];
    const int b0o = b0 * AS, b1o = b1 * AS;
    const int lb  = stid >> 2;               // loader: row
    const int lf0 = stid & 3;                // loader: float4 phase
    const int barid = slice + 1;             // named barrier per slice

    // chunk id for slice step j: slice0 -> {0..3, 8..11}, slice1 -> {4..7, 12..15}
    #define CHUNK_ID(j) (slice * 4 + ((j) & 3) + (((j) >= 4) ? 8 : 0))

    // phase p: group1 computes layer0(t=p) for p<T; group0 computes layer1(t=p-1) for p>=1
    for (int p = 0; p <= TT; ++p) {
        const bool active = (group == 1) ? (p < TT) : (p >= 1);
        if (active) {
            const int t = (group == 1) ? p : (p - 1);
            const float* srcI = (group == 1) ? (ins + (size_t)t * BB * WW)
                                             : &g_h0[(p - 1) & 1][0];
            const float* srcH = (group == 1) ? &g_h0[(p == 0) ? 1 : ((p - 1) & 1)][0]
                                             : &g_h1[(p - 1) & 1][0];
            const bool zeroH = (group == 1) ? (p == 0) : (p == 1);

            if (tid < BB) {
                float m = 0.0f;
                if (!zeroH) m = reset_mask(resets, rmode, t * BB + tid);
                rm[tid] = m;
            }
            __syncthreads();                 // rm visible to both slices

            ull r0 = 0, r1 = 0, z0 = 0, z1 = 0;
            ull ni0 = 0, ni1 = 0, nh0 = 0, nh1 = 0;

            // ---- stage this slice's first chunk (always an I-half chunk, pm=1) ----
            {
                const int c0 = CHUNK_ID(0);  // slice*4 -> always < 8
                const float* src = srcI;
                const int kOff = c0 * CHUNK;
#pragma unroll
                for (int it = 0; it < 4; ++it) {
                    int f4 = lf0 + it * 4;
                    float4 v = __ldcg((const float4*)(src + (size_t)lb * WW + kOff + f4 * 4));
                    *(float4*)(Asl + lb * AS + f4 * 4) = v;
                }
            }
            slice_bar(barid);

            float4 pf[4]; float pm = 1.0f;
            for (int j = 0; j < NCH_S; ++j) {
                const int c = CHUNK_ID(j);
                if (j + 1 < NCH_S) {         // prefetch next chunk into registers
                    const int cn = CHUNK_ID(j + 1);
                    const float* src = (cn < 8) ? srcI : srcH;
                    const int kOff = (cn < 8) ? cn * CHUNK : (cn - 8) * CHUNK;
                    pm = (cn < 8) ? 1.0f : rm[lb];
#pragma unroll
                    for (int it = 0; it < 4; ++it) {
                        int f4 = lf0 + it * 4;
                        pf[it] = __ldcg((const float4*)(src + (size_t)lb * WW + kOff + f4 * 4));
                    }
                }
                const float* As = Asl + (j & 1) * BB * AS;
                if (c < 8) mma_chunk(As, wr, wz, wn, c * CHUNK, b0o, b1o, r0, r1, z0, z1, ni0, ni1);
                else       mma_chunk(As, wr, wz, wn, c * CHUNK, b0o, b1o, r0, r1, z0, z1, nh0, nh1);
                if (j + 1 < NCH_S) {         // commit prefetch to the other buffer
                    float* dst = Asl + ((j + 1) & 1) * BB * AS;
#pragma unroll
                    for (int it = 0; it < 4; ++it) {
                        int f4 = lf0 + it * 4;
                        float4 v = pf[it];
                        *(float4*)(dst + lb * AS + f4 * 4) =
                            make_float4(v.x * pm, v.y * pm, v.z * pm, v.w * pm);
                    }
                }
                slice_bar(barid);
            }

            // ---- cross-slice reduction: slice1 publishes partials as floats ----
            if (slice == 1) {
                float* rd = red + stid * 8;
                rd[0] = hadd2(r0);  rd[1] = hadd2(r1);
                rd[2] = hadd2(z0);  rd[3] = hadd2(z1);
                rd[4] = hadd2(ni0); rd[5] = hadd2(ni1);
                rd[6] = hadd2(nh0); rd[7] = hadd2(nh1);
            }
            __syncthreads();

            if (slice == 0) {
                const float* rd = red + stid * 8;
                const float m0 = rm[b0], m1 = rm[b1];
                const float hp0 = __ldcg(srcH + b0 * WW + w) * m0;
                const float hp1 = __ldcg(srcH + b1 * WW + w) * m1;
                const float gr0 = bir + hadd2(r0)  + rd[0];
                const float gr1 = bir + hadd2(r1)  + rd[1];
                const float gz0 = biz + hadd2(z0)  + rd[2];
                const float gz1 = biz + hadd2(z1)  + rd[3];
                const float gi0 = bin + hadd2(ni0) + rd[4];
                const float gi1 = bin + hadd2(ni1) + rd[5];
                const float gh0 = hadd2(nh0) + rd[6];
                const float gh1 = hadd2(nh1) + rd[7];
                const float rr0 = 1.0f / (1.0f + expf(-gr0));
                const float rr1 = 1.0f / (1.0f + expf(-gr1));
                const float zz0 = 1.0f / (1.0f + expf(-gz0));
                const float zz1 = 1.0f / (1.0f + expf(-gz1));
                const float nn0 = tanhf(gi0 + rr0 * (gh0 + bhnw));
                const float nn1 = tanhf(gi1 + rr1 * (gh1 + bhnw));
                const float hnew0 = (1.0f - zz0) * nn0 + zz0 * hp0;
                const float hnew1 = (1.0f - zz1) * nn1 + zz1 * hp1;

                float* dst = (group == 1) ? &g_h0[p & 1][0] : &g_h1[p & 1][0];
                dst[b0 * WW + w] = hnew0;
                dst[b1 * WW + w] = hnew1;
                if (group == 0) {
                    out_ys[(size_t)t * BB * WW + b0 * WW + w] = hnew0;
                    out_ys[(size_t)t * BB * WW + b1 * WW + w] = hnew1;
                    if (p == TT) {               // final h1 carry
                        out_carry[1 * BB * WW + b0 * WW + w] = hnew0;
                        out_carry[1 * BB * WW + b1 * WW + w] = hnew1;
                    }
                } else if (p == TT - 1) {        // final h0 carry
                    out_carry[b0 * WW + w] = hnew0;
                    out_carry[b1 * WW + w] = hnew1;
                }
            }
        }

        // ---- grid barrier (self-resetting counter + monotonic generation) ----
        __syncthreads();
        if (tid == 0) {
            __threadfence();
            unsigned a = atomicAdd(&g_cnt, 1);
            gen += 1;
            if (a == GRID - 1) {
                g_cnt = 0;
                __threadfence();
                g_gen = gen;
            } else {
                while (g_gen < gen) { __nanosleep(20); }
                __threadfence();
            }
        }
        __syncthreads();
    }
}

extern "C" void kernel_launch(void* const* d_in, const int* in_sizes, int n_in,
                              void* d_out, int out_size)
{
    const float* ins    = (const float*)d_in[0];
    const void*  resets = (const void*)d_in[1];
    const float* Wi     = (const float*)d_in[2];
    const float* bi     = (const float*)d_in[3];
    const float* Wh     = (const float*)d_in[4];
    const float* bhn    = (const float*)d_in[5];
    float*       out    = (float*)d_out;

    sniff_resets_kernel<<<1, 256>>>((const unsigned*)resets);

    cudaFuncSetAttribute(gru_scan_kernel,
                         cudaFuncAttributeMaxDynamicSharedMemorySize, SMEM_BYTES);
    gru_scan_kernel<<<GRID, NTH, SMEM_BYTES>>>(ins, resets, Wi, bi, Wh, bhn, out);
}

// round 5
// speedup vs baseline: 1.0585x; 1.0011x over previous
#include <cuda_runtime.h>

typedef unsigned long long ull;

// ---------------- problem constants ----------------
#define TT    1024
#define BB    64
#define WW    512
#define W3    1536
#define LL    2

// ---------------- kernel config --------------------
#define GRID    128     // 64 CTAs per GEMM-group; all co-resident, 1 CTA/SM
#define NTH     512     // 2 K-slices x 256
#define NGC     8       // gate-triples per CTA (64*8 = 512 columns)
#define NCOLS   (NGC*3) // 24 weight columns per CTA
#define CHUNK   64      // K-chunk staged in smem
#define NCH_S   8       // chunks per K-slice (16 total / 2 slices)
#define AS      68      // A smem row stride (pad -> conflict-free, 16B-aligned)
#define WS      1028    // W smem row stride (pad -> conflict-free, 16B-aligned)

// smem layout (floats): W | A[2 slices][2 bufs][BB*AS] | rm[BB] | red[256*8]
#define SMEM_W      (NCOLS*WS)
#define SMEM_A      (SMEM_W)
#define SMEM_RM     (SMEM_A + 4*BB*AS)
#define SMEM_RED    (SMEM_RM + BB)
#define SMEM_FLOATS (SMEM_RED + 256*8)
#define SMEM_BYTES  (SMEM_FLOATS * 4)

// ---------------- persistent device state ----------
__device__ float g_h0[2][BB * WW];      // double-buffered layer-0 hidden
__device__ float g_h1[2][BB * WW];      // double-buffered layer-1 hidden
__device__ unsigned g_cnt = 0;          // barrier arrival counter (self-resetting)
__device__ volatile unsigned g_gen = 0; // barrier generation (monotonic across launches)
__device__ int g_reset_mode = 0;        // 0=uint8/bool, 1=int32, 2=float32

// ---------------- reset dtype sniffing --------------
__global__ void sniff_resets_kernel(const unsigned* __restrict__ r)
{
    __shared__ unsigned red[256];
    unsigned m = 0;
    for (int i = threadIdx.x; i < (TT * BB) / 4; i += 256)
        m = max(m, r[i]);
    red[threadIdx.x] = m;
    __syncthreads();
    for (int s = 128; s > 0; s >>= 1) {
        if (threadIdx.x < s) red[threadIdx.x] = max(red[threadIdx.x], red[threadIdx.x + s]);
        __syncthreads();
    }
    if (threadIdx.x == 0) {
        unsigned mx = red[0];
        g_reset_mode = (mx <= 1u) ? 1 : (mx >= 0x10000000u ? 2 : 0);
    }
}

__device__ __forceinline__ float reset_mask(const void* r, int mode, int idx)
{
    if (mode == 1) return ((const int*)r)[idx] != 0 ? 0.0f : 1.0f;
    if (mode == 2) return ((const float*)r)[idx] != 0.0f ? 0.0f : 1.0f;
    return ((const unsigned char*)r)[idx] != 0 ? 0.0f : 1.0f;
}

// ---------------- packed f32x2 FMA ------------------
__device__ __forceinline__ void ffma2(ull& acc, ull a, ull b)
{
    asm("fma.rn.f32x2 %0, %1, %2, %0;" : "+l"(acc) : "l"(a), "l"(b));
}
__device__ __forceinline__ float hadd2(ull v)
{
    return __uint_as_float((unsigned)v) + __uint_as_float((unsigned)(v >> 32));
}

// slice-scoped named barrier (256 threads each)
__device__ __forceinline__ void slice_bar(int id)
{
    asm volatile("bar.sync %0, %1;" :: "r"(id), "r"(256) : "memory");
}

// --------------- inner product over one K-chunk -----
// per thread: 2 batch rows x 3 gate columns, K-packed by 2 via f32x2
__device__ __forceinline__ void mma_chunk(
    const float* __restrict__ As,
    const float* __restrict__ wr, const float* __restrict__ wz, const float* __restrict__ wn,
    int kbase, int b0o, int b1o,
    ull& r0, ull& r1, ull& z0, ull& z1, ull& n0, ull& n1)
{
#pragma unroll
    for (int kk = 0; kk < CHUNK; kk += 4) {
        float4 a0 = *(const float4*)(As + b0o + kk);
        float4 a1 = *(const float4*)(As + b1o + kk);
        float4 fr = *(const float4*)(wr + kbase + kk);
        float4 fz = *(const float4*)(wz + kbase + kk);
        float4 fn = *(const float4*)(wn + kbase + kk);
        const ull* a0p = (const ull*)&a0;
        const ull* a1p = (const ull*)&a1;
        const ull* frp = (const ull*)&fr;
        const ull* fzp = (const ull*)&fz;
        const ull* fnp = (const ull*)&fn;
        ffma2(r0, a0p[0], frp[0]); ffma2(r0, a0p[1], frp[1]);
        ffma2(r1, a1p[0], frp[0]); ffma2(r1, a1p[1], frp[1]);
        ffma2(z0, a0p[0], fzp[0]); ffma2(z0, a0p[1], fzp[1]);
        ffma2(z1, a1p[0], fzp[0]); ffma2(z1, a1p[1], fzp[1]);
        ffma2(n0, a0p[0], fnp[0]); ffma2(n0, a0p[1], fnp[1]);
        ffma2(n1, a1p[0], fnp[0]); ffma2(n1, a1p[1], fnp[1]);
    }
}

__global__ void __launch_bounds__(NTH, 1)
gru_scan_kernel(const float* __restrict__ ins,
                const void* __restrict__ resets,
                const float* __restrict__ Wi, const float* __restrict__ bi,
                const float* __restrict__ Wh, const float* __restrict__ bhn,
                float* __restrict__ out)
{
    extern __shared__ float smem[];
    float* Wsm = smem;                       // [NCOLS][WS]   transposed weights
    float* rm  = smem + SMEM_RM;             // [BB]          per-batch reset mask
    float* red = smem + SMEM_RED;            // [256][8]      slice-1 partial sums

    const int tid   = threadIdx.x;
    const int slice = tid >> 8;              // K-slice 0/1
    const int stid  = tid & 255;
    const int cta   = blockIdx.x;
    const int group = cta >> 6;              // 0: layer-1 task, 1: layer-0 task
    const int lyr   = (group == 0) ? 1 : 0;
    const int gwBase = (cta & 63) * NGC;
    const int tn = stid & 7;                 // gate-triple within CTA
    const int tm = stid >> 3;                // batch pair
    const int b0 = tm * 2, b1 = tm * 2 + 1;
    const int w  = gwBase + tn;              // global gate column [0,512)
    const int rmode = g_reset_mode;

    float* Asl = smem + SMEM_A + slice * (2 * BB * AS);  // this slice's A double buffer

    // ---- one-time: load this CTA's weight slice into smem, transposed [n][k] ----
    const float* WiL = Wi + (size_t)lyr * WW * W3;
    const float* WhL = Wh + (size_t)lyr * WW * W3;
    for (int idx = tid; idx < NCOLS * WW * 2; idx += NTH) {
        int n = idx % NCOLS;
        int k = idx / NCOLS;
        int gl = n / 3, gate = n - gl * 3;
        int c = gwBase + gl + gate * WW;
        float v = (k < WW) ? WiL[(size_t)k * W3 + c] : WhL[(size_t)(k - WW) * W3 + c];
        Wsm[n * WS + k] = v;
    }
    const float bir  = bi[lyr * W3 + w];
    const float biz  = bi[lyr * W3 + WW + w];
    const float bin  = bi[lyr * W3 + 2 * WW + w];
    const float bhnw = bhn[lyr * WW + w];

    unsigned gen = 0;
    if (tid == 0) gen = g_gen;               // per-launch barrier base (monotonic)
    __syncthreads();                         // weights + gen ready

    float* out_carry = out;                  // [L][B][W]
    float* out_ys    = out + LL * BB * WW;   // [T][B][W]

    const float* wr = &Wsm[(tn * 3 + 0) * WS];
    const float* wz = &Wsm[(tn * 3 + 1) * WS];
    const float* wn = &Wsm[(tn * 3 + 2) * WS];
    const int b0o = b0 * AS, b1o = b1 * AS;
    const int lb  = stid >> 2;               // loader: row
    const int lf0 = stid & 3;                // loader: float4 phase
    const int barid = slice + 1;             // named barrier per slice

    // chunk id for slice step j: slice0 -> {0..3, 8..11}, slice1 -> {4..7, 12..15}
    #define CHUNK_ID(j) (slice * 4 + ((j) & 3) + (((j) >= 4) ? 8 : 0))

    // phase p: group1 computes layer0(t=p) for p<T; group0 computes layer1(t=p-1) for p>=1
    for (int p = 0; p <= TT; ++p) {
        const bool active = (group == 1) ? (p < TT) : (p >= 1);
        if (active) {
            const int t = (group == 1) ? p : (p - 1);
            const float* srcI = (group == 1) ? (ins + (size_t)t * BB * WW)
                                             : &g_h0[(p - 1) & 1][0];
            const float* srcH = (group == 1) ? &g_h0[(p == 0) ? 1 : ((p - 1) & 1)][0]
                                             : &g_h1[(p - 1) & 1][0];
            const bool zeroH = (group == 1) ? (p == 0) : (p == 1);

            if (tid < BB) {
                float m = 0.0f;
                if (!zeroH) m = reset_mask(resets, rmode, t * BB + tid);
                rm[tid] = m;
            }
            __syncthreads();                 // rm visible to both slices

            ull r0 = 0, r1 = 0, z0 = 0, z1 = 0;
            ull ni0 = 0, ni1 = 0, nh0 = 0, nh1 = 0;

            // ---- stage this slice's first chunk (always an I-half chunk, pm=1) ----
            {
                const int c0 = CHUNK_ID(0);  // slice*4 -> always < 8
                const float* src = srcI;
                const int kOff = c0 * CHUNK;
#pragma unroll
                for (int it = 0; it < 4; ++it) {
                    int f4 = lf0 + it * 4;
                    float4 v = __ldcg((const float4*)(src + (size_t)lb * WW + kOff + f4 * 4));
                    *(float4*)(Asl + lb * AS + f4 * 4) = v;
                }
            }
            slice_bar(barid);

            float4 pf[4]; float pm = 1.0f;
            for (int j = 0; j < NCH_S; ++j) {
                const int c = CHUNK_ID(j);
                if (j + 1 < NCH_S) {         // prefetch next chunk into registers
                    const int cn = CHUNK_ID(j + 1);
                    const float* src = (cn < 8) ? srcI : srcH;
                    const int kOff = (cn < 8) ? cn * CHUNK : (cn - 8) * CHUNK;
                    pm = (cn < 8) ? 1.0f : rm[lb];
#pragma unroll
                    for (int it = 0; it < 4; ++it) {
                        int f4 = lf0 + it * 4;
                        pf[it] = __ldcg((const float4*)(src + (size_t)lb * WW + kOff + f4 * 4));
                    }
                }
                const float* As = Asl + (j & 1) * BB * AS;
                if (c < 8) mma_chunk(As, wr, wz, wn, c * CHUNK, b0o, b1o, r0, r1, z0, z1, ni0, ni1);
                else       mma_chunk(As, wr, wz, wn, c * CHUNK, b0o, b1o, r0, r1, z0, z1, nh0, nh1);
                if (j + 1 < NCH_S) {         // commit prefetch to the other buffer
                    float* dst = Asl + ((j + 1) & 1) * BB * AS;
#pragma unroll
                    for (int it = 0; it < 4; ++it) {
                        int f4 = lf0 + it * 4;
                        float4 v = pf[it];
                        *(float4*)(dst + lb * AS + f4 * 4) =
                            make_float4(v.x * pm, v.y * pm, v.z * pm, v.w * pm);
                    }
                }
                slice_bar(barid);
            }

            // ---- cross-slice reduction: slice1 publishes partials as floats ----
            if (slice == 1) {
                float* rd = red + stid * 8;
                rd[0] = hadd2(r0);  rd[1] = hadd2(r1);
                rd[2] = hadd2(z0);  rd[3] = hadd2(z1);
                rd[4] = hadd2(ni0); rd[5] = hadd2(ni1);
                rd[6] = hadd2(nh0); rd[7] = hadd2(nh1);
            }
            __syncthreads();

            if (slice == 0) {
                const float* rd = red + stid * 8;
                const float m0 = rm[b0], m1 = rm[b1];
                const float hp0 = __ldcg(srcH + b0 * WW + w) * m0;
                const float hp1 = __ldcg(srcH + b1 * WW + w) * m1;
                const float gr0 = bir + hadd2(r0)  + rd[0];
                const float gr1 = bir + hadd2(r1)  + rd[1];
                const float gz0 = biz + hadd2(z0)  + rd[2];
                const float gz1 = biz + hadd2(z1)  + rd[3];
                const float gi0 = bin + hadd2(ni0) + rd[4];
                const float gi1 = bin + hadd2(ni1) + rd[5];
                const float gh0 = hadd2(nh0) + rd[6];
                const float gh1 = hadd2(nh1) + rd[7];
                const float rr0 = 1.0f / (1.0f + expf(-gr0));
                const float rr1 = 1.0f / (1.0f + expf(-gr1));
                const float zz0 = 1.0f / (1.0f + expf(-gz0));
                const float zz1 = 1.0f / (1.0f + expf(-gz1));
                const float nn0 = tanhf(gi0 + rr0 * (gh0 + bhnw));
                const float nn1 = tanhf(gi1 + rr1 * (gh1 + bhnw));
                const float hnew0 = (1.0f - zz0) * nn0 + zz0 * hp0;
                const float hnew1 = (1.0f - zz1) * nn1 + zz1 * hp1;

                float* dst = (group == 1) ? &g_h0[p & 1][0] : &g_h1[p & 1][0];
                dst[b0 * WW + w] = hnew0;
                dst[b1 * WW + w] = hnew1;
                if (group == 0) {
                    out_ys[(size_t)t * BB * WW + b0 * WW + w] = hnew0;
                    out_ys[(size_t)t * BB * WW + b1 * WW + w] = hnew1;
                    if (p == TT) {               // final h1 carry
                        out_carry[1 * BB * WW + b0 * WW + w] = hnew0;
                        out_carry[1 * BB * WW + b1 * WW + w] = hnew1;
                    }
                } else if (p == TT - 1) {        // final h0 carry
                    out_carry[b0 * WW + w] = hnew0;
                    out_carry[b1 * WW + w] = hnew1;
                }
            }
        }

        // ---- grid barrier (self-resetting counter + monotonic generation) ----
        __syncthreads();
        if (tid == 0) {
            __threadfence();
            unsigned a = atomicAdd(&g_cnt, 1);
            gen += 1;
            if (a == GRID - 1) {
                g_cnt = 0;
                __threadfence();
                g_gen = gen;
            } else {
                while (g_gen < gen) { __nanosleep(20); }
                __threadfence();
            }
        }
        __syncthreads();
    }
}

extern "C" void kernel_launch(void* const* d_in, const int* in_sizes, int n_in,
                              void* d_out, int out_size)
{
    const float* ins    = (const float*)d_in[0];
    const void*  resets = (const void*)d_in[1];
    const float* Wi     = (const float*)d_in[2];
    const float* bi     = (const float*)d_in[3];
    const float* Wh     = (const float*)d_in[4];
    const float* bhn    = (const float*)d_in[5];
    float*       out    = (float*)d_out;

    sniff_resets_kernel<<<1, 256>>>((const unsigned*)resets);

    cudaFuncSetAttribute(gru_scan_kernel,
                         cudaFuncAttributeMaxDynamicSharedMemorySize, SMEM_BYTES);
    gru_scan_kernel<<<GRID, NTH, SMEM_BYTES>>>(ins, resets, Wi, bi, Wh, bhn, out);
}

// round 6
// speedup vs baseline: 1.9718x; 1.8628x over previous
#include <cuda_runtime.h>

typedef unsigned long long ull;

#define TT 1024
#define BB 64
#define WW 512
#define W3 1536
#define LL 2

#define GRID 128
#define NTH  256
#define WS   1028            // weight smem row stride (16B-aligned, conflict-free)
#define PS   49              // partials stride (gcd(49,32)=1 -> conflict-free)

#define SM_RM   (24*WS)
#define SM_BIA  (SM_RM + BB)
#define SM_BHN  (SM_BIA + 24)
#define SM_PART (SM_BHN + 8)
#define SM_TOT  (SM_PART + NTH*PS)
#define SMEM_BYTES (SM_TOT*4)

__device__ __align__(256) float g_insT[TT][WW][BB]; // ins transposed [t][k][b]
__device__ __align__(256) float g_h0T[2][WW][BB];   // layer-0 hidden [w][b]
__device__ __align__(256) float g_h1T[2][WW][BB];   // layer-1 hidden [w][b]
__device__ unsigned g_cnt = 0;
__device__ volatile unsigned g_gen = 0;
__device__ int g_reset_mode = 0;

__global__ void sniff_resets_kernel(const unsigned* __restrict__ r)
{
    __shared__ unsigned red[256];
    unsigned m = 0;
    for (int i = threadIdx.x; i < (TT * BB) / 4; i += 256) m = max(m, r[i]);
    red[threadIdx.x] = m;
    __syncthreads();
    for (int s = 128; s > 0; s >>= 1) {
        if (threadIdx.x < s) red[threadIdx.x] = max(red[threadIdx.x], red[threadIdx.x + s]);
        __syncthreads();
    }
    if (threadIdx.x == 0) {
        unsigned mx = red[0];
        g_reset_mode = (mx <= 1u) ? 1 : (mx >= 0x10000000u ? 2 : 0);
    }
}

__device__ __forceinline__ float reset_mask(const void* r, int mode, int idx)
{
    if (mode == 1) return ((const int*)r)[idx] != 0 ? 0.0f : 1.0f;
    if (mode == 2) return ((const float*)r)[idx] != 0.0f ? 0.0f : 1.0f;
    return ((const unsigned char*)r)[idx] != 0 ? 0.0f : 1.0f;
}

// transpose ins: [t][b][w] -> [t][w][b]
__global__ void transpose_ins_kernel(const float* __restrict__ ins)
{
    __shared__ float tile[64][65];
    const int t  = blockIdx.x >> 3;
    const int w0 = (blockIdx.x & 7) * 64;
    const float* src = ins + (size_t)t * BB * WW;
    for (int i = threadIdx.x; i < 64 * 64; i += 256) {
        int b = i >> 6, w = i & 63;
        tile[b][w] = src[b * WW + w0 + w];
    }
    __syncthreads();
    float* dst = &g_insT[t][w0][0];
    for (int i = threadIdx.x; i < 64 * 64; i += 256) {
        int w = i >> 6, b = i & 63;
        dst[w * BB + b] = tile[b][w];
    }
}

__device__ __forceinline__ void ffma2(ull& acc, ull a, ull b)
{ asm("fma.rn.f32x2 %0, %1, %2, %0;" : "+l"(acc) : "l"(a), "l"(b)); }
__device__ __forceinline__ ull dup2(float s)
{ ull r; asm("mov.b64 %0, {%1, %1};" : "=l"(r) : "f"(s)); return r; }
__device__ __forceinline__ float lo2(ull v) { return __uint_as_float((unsigned)v); }
__device__ __forceinline__ float hi2(ull v) { return __uint_as_float((unsigned)(v >> 32)); }
__device__ __forceinline__ float4 ldcg4(const float* p) { return __ldcg((const float4*)p); }

__global__ void __launch_bounds__(NTH, 1)
gru_scan_kernel(const void* __restrict__ resets,
                const float* __restrict__ Wi, const float* __restrict__ bi,
                const float* __restrict__ Wh, const float* __restrict__ bhn,
                float* __restrict__ out)
{
    extern __shared__ float smem[];
    float* Wsm  = smem;              // [24][WS]   weights, [col][k]
    float* rm   = smem + SM_RM;      // [64]
    float* bia  = smem + SM_BIA;     // [24]
    float* bhna = smem + SM_BHN;     // [8]
    float* part = smem + SM_PART;    // [256][PS]

    const int tid  = threadIdx.x;
    const int lane = tid & 31;
    const int warp = tid >> 5;
    const int cta  = blockIdx.x;
    const int group = cta >> 6;          // 0: layer-1 task, 1: layer-0 task
    const int lyr  = group ? 0 : 1;
    const int gwBase = (cta & 63) * 8;   // 8 gate-triples per CTA
    const int rg = lane >> 2;            // batch row-group: rows rg*8..+7
    const int cg = lane & 3;             // col-group: cols cg*6..+5
    const int half = warp >> 2;          // 0 = input half, 1 = hidden half
    const int kb   = (warp & 3) * 128;   // k base within half
    const int rmode = g_reset_mode;

    // ---- one-time weights/biases to smem ----
    const float* WiL = Wi + (size_t)lyr * WW * W3;
    const float* WhL = Wh + (size_t)lyr * WW * W3;
    for (int idx = tid; idx < 24 * 1024; idx += NTH) {
        int c = idx % 24, k = idx / 24;
        int ttl = c / 3, g = c - ttl * 3;
        int gc = gwBase + ttl + g * WW;
        Wsm[c * WS + k] = (k < WW) ? WiL[(size_t)k * W3 + gc]
                                   : WhL[(size_t)(k - WW) * W3 + gc];
    }
    if (tid < 24) { int ttl = tid / 3, g = tid - ttl * 3;
                    bia[tid] = bi[lyr * W3 + g * WW + gwBase + ttl]; }
    if (tid < 8)  bhna[tid] = bhn[lyr * WW + gwBase + tid];

    unsigned gen = 0;
    if (tid == 0) gen = g_gen;
    __syncthreads();

    float* out_carry = out;
    float* out_ys    = out + LL * BB * WW;
    const float* wB = Wsm + (cg * 6) * WS + half * 512 + kb;

    for (int p = 0; p <= TT; ++p) {
        const bool active = group ? (p < TT) : (p >= 1);
        const int t = group ? p : (p - 1);
        const float* srcH = group ? &g_h0T[(p == 0) ? 1 : ((p - 1) & 1)][0][0]
                                  : &g_h1T[(p == 1) ? 1 : ((p - 1) & 1)][0][0];
        if (active) {
            const bool zeroH = group ? (p == 0) : (p == 1);
            const float* srcI = group ? &g_insT[t][0][0] : &g_h0T[(p - 1) & 1][0][0];

            if (tid < BB)
                rm[tid] = zeroH ? 0.0f : reset_mask(resets, rmode, t * BB + tid);

            if (group && p + 1 < TT) {   // L2 prefetch next timestep slice
                const float* nb = &g_insT[p + 1][0][0] + (cta & 63) * 512 + tid * 2;
                asm volatile("prefetch.global.L2 [%0];" :: "l"(nb));
            }

            const float* srcA = half ? srcH : srcI;
            const float* aB = srcA + kb * BB + rg * 8;

            ull acc[4][6];
#pragma unroll
            for (int i = 0; i < 4; ++i)
#pragma unroll
                for (int j = 0; j < 6; ++j) acc[i][j] = 0ull;

            float4 a[2][8], wv[2][6];
#pragma unroll
            for (int x = 0; x < 8; ++x) a[0][x] = ldcg4(aB + (x >> 1) * BB + (x & 1) * 4);
#pragma unroll
            for (int j = 0; j < 6; ++j) wv[0][j] = *(const float4*)(wB + j * WS);

#pragma unroll 2
            for (int st = 0; st < 32; ++st) {
                const int cur = st & 1;
                if (st + 1 < 32) {
#pragma unroll
                    for (int x = 0; x < 8; ++x)
                        a[cur ^ 1][x] = ldcg4(aB + ((st + 1) * 4 + (x >> 1)) * BB + (x & 1) * 4);
#pragma unroll
                    for (int j = 0; j < 6; ++j)
                        wv[cur ^ 1][j] = *(const float4*)(wB + j * WS + (st + 1) * 4);
                }
#pragma unroll
                for (int kk = 0; kk < 4; ++kk) {
                    const ull* ap = (const ull*)&a[cur][kk * 2];  // 4 batch-pair ulls
#pragma unroll
                    for (int j = 0; j < 6; ++j) {
                        ull w2 = dup2(((const float*)&wv[cur][j])[kk]);
                        ffma2(acc[0][j], ap[0], w2);
                        ffma2(acc[1][j], ap[1], w2);
                        ffma2(acc[2][j], ap[2], w2);
                        ffma2(acc[3][j], ap[3], w2);
                    }
                }
            }

            // publish partials (stride 49 -> conflict-free)
            float* mp = part + tid * PS;
#pragma unroll
            for (int ip = 0; ip < 4; ++ip)
#pragma unroll
                for (int j = 0; j < 6; ++j) {
                    mp[(2 * ip) * 6 + j]     = lo2(acc[ip][j]);
                    mp[(2 * ip + 1) * 6 + j] = hi2(acc[ip][j]);
                }
        }

        __syncthreads();

        if (active) {
#pragma unroll
            for (int e = 0; e < 2; ++e) {
                const int idx = tid * 2 + e;        // 0..511
                const int b = idx >> 3, ttl = idx & 7;
                const float m = rm[b];
                const int tbase = (b >> 3) * 4;     // rg*4
                const int roff  = (b & 7) * 6;
                float si[3], sh[3];
#pragma unroll
                for (int g = 0; g < 3; ++g) {
                    const int c = ttl * 3 + g;
                    const float* pp = part + (tbase + c / 6) * PS + roff + c % 6;
                    si[g] = pp[0] + pp[32 * PS] + pp[64 * PS] + pp[96 * PS];
                    sh[g] = pp[128 * PS] + pp[160 * PS] + pp[192 * PS] + pp[224 * PS];
                }
                const float r = 1.0f / (1.0f + expf(-(bia[ttl * 3 + 0] + si[0] + m * sh[0])));
                const float z = 1.0f / (1.0f + expf(-(bia[ttl * 3 + 1] + si[1] + m * sh[1])));
                const float n = tanhf(bia[ttl * 3 + 2] + si[2] + r * (m * sh[2] + bhna[ttl]));
                const int w = gwBase + ttl;
                const float hp = m * __ldcg(srcH + w * BB + b);
                const float h = (1.0f - z) * n + z * hp;

                float* dstT = group ? &g_h0T[p & 1][0][0] : &g_h1T[p & 1][0][0];
                dstT[w * BB + b] = h;
                if (group == 0) {
                    out_ys[(size_t)t * BB * WW + b * WW + w] = h;
                    if (p == TT) out_carry[BB * WW + b * WW + w] = h;
                } else if (p == TT - 1) {
                    out_carry[b * WW + w] = h;
                }
            }
        }

        // grid barrier
        __syncthreads();
        if (tid == 0) {
            __threadfence();
            unsigned a = atomicAdd(&g_cnt, 1);
            gen += 1;
            if (a == GRID - 1) {
                g_cnt = 0;
                __threadfence();
                g_gen = gen;
            } else {
                while (g_gen < gen) { __nanosleep(20); }
                __threadfence();
            }
        }
        __syncthreads();
    }
}

extern "C" void kernel_launch(void* const* d_in, const int* in_sizes, int n_in,
                              void* d_out, int out_size)
{
    const float* ins    = (const float*)d_in[0];
    const void*  resets = (const void*)d_in[1];
    const float* Wi     = (const float*)d_in[2];
    const float* bi     = (const float*)d_in[3];
    const float* Wh     = (const float*)d_in[4];
    const float* bhn    = (const float*)d_in[5];
    float*       out    = (float*)d_out;

    sniff_resets_kernel<<<1, 256>>>((const unsigned*)resets);
    transpose_ins_kernel<<<TT * 8, 256>>>(ins);

    cudaFuncSetAttribute(gru_scan_kernel,
                         cudaFuncAttributeMaxDynamicSharedMemorySize, SMEM_BYTES);
    gru_scan_kernel<<<GRID, NTH, SMEM_BYTES>>>(resets, Wi, bi, Wh, bhn, out);
}